// round 1
// baseline (speedup 1.0000x reference)
#include <cuda_runtime.h>
#include <math.h>

// ---------------- problem constants ----------------
#define B_  32
#define T_  256
#define D_  512
#define NH_ 8
#define DK_ 64
#define L_  2
#define ML_ 25

// ---------------- scratch (device globals; no allocation allowed) ----------------
__device__ float g_enc[B_*T_*D_];
__device__ float g_tmp[B_*T_*D_];
__device__ float g_q  [B_*T_*D_];
__device__ float g_k  [B_*T_*D_];
__device__ float g_v  [B_*T_*D_];
__device__ float g_o  [B_*T_*D_];
__device__ float g_p  [B_*NH_*T_*T_];

__device__ __forceinline__ float tanh_fast(float x) {
    float y;
    asm("tanh.approx.f32 %0, %1;" : "=f"(y) : "f"(x));
    return y;
}

// ---------------- prep: enc[b,t,d] = x[b,d,t]*sqrt(D) + pos[ewp[t], d] ----------------
__global__ void prep_kernel(const float* __restrict__ x, const float* __restrict__ pos,
                            const int* __restrict__ ewp, float* __restrict__ enc)
{
    __shared__ float tile[32][33];
    int b  = blockIdx.z;
    int d0 = blockIdx.x * 32, t0 = blockIdx.y * 32;
    int tx = threadIdx.x, ty = threadIdx.y;
    const float* xb = x + (long long)b * D_ * T_;
    #pragma unroll
    for (int i = 0; i < 4; i++) {
        int d = ty + i * 8;
        tile[d][tx] = xb[(long long)(d0 + d) * T_ + t0 + tx];
    }
    __syncthreads();
    #pragma unroll
    for (int i = 0; i < 4; i++) {
        int tl = ty + i * 8;
        int t = t0 + tl, d = d0 + tx;
        int pr = ewp[t];
        enc[(((long long)b * T_) + t) * D_ + d] =
            tile[tx][tl] * 22.62741699796952f + pos[(long long)pr * D_ + d];
    }
}

// ---------------- layernorm over D=512, one warp per row ----------------
__global__ void ln_kernel(const float* __restrict__ in, float* __restrict__ out,
                          const float* __restrict__ gs, const float* __restrict__ gb)
{
    int row  = blockIdx.x * 8 + threadIdx.y;
    int lane = threadIdx.x;
    const float* r = in + (long long)row * D_;
    float4 xv[4];
    #pragma unroll
    for (int j = 0; j < 4; j++)
        xv[j] = *reinterpret_cast<const float4*>(&r[(j * 32 + lane) * 4]);
    float s = 0.f;
    #pragma unroll
    for (int j = 0; j < 4; j++) s += xv[j].x + xv[j].y + xv[j].z + xv[j].w;
    #pragma unroll
    for (int o = 16; o; o >>= 1) s += __shfl_xor_sync(0xffffffffu, s, o);
    float mean = s * (1.0f / D_);
    float vs = 0.f;
    #pragma unroll
    for (int j = 0; j < 4; j++) {
        float a = xv[j].x - mean, b2 = xv[j].y - mean, c = xv[j].z - mean, d = xv[j].w - mean;
        vs += a * a + b2 * b2 + c * c + d * d;
    }
    #pragma unroll
    for (int o = 16; o; o >>= 1) vs += __shfl_xor_sync(0xffffffffu, vs, o);
    float rstd = rsqrtf(vs * (1.0f / D_) + 1e-5f);
    float* w = out + (long long)row * D_;
    #pragma unroll
    for (int j = 0; j < 4; j++) {
        int c0 = (j * 32 + lane) * 4;
        float4 sv = *reinterpret_cast<const float4*>(&gs[c0]);
        float4 bv = *reinterpret_cast<const float4*>(&gb[c0]);
        float4 t;
        t.x = (xv[j].x - mean) * rstd * sv.x + bv.x;
        t.y = (xv[j].y - mean) * rstd * sv.y + bv.y;
        t.z = (xv[j].z - mean) * rstd * sv.z + bv.z;
        t.w = (xv[j].w - mean) * rstd * sv.w + bv.w;
        *reinterpret_cast<float4*>(&w[c0]) = t;
    }
}

// ---------------- softmax over rows of length 256 (scale folded into GEMM alpha) ----------------
__global__ void softmax_kernel(float* __restrict__ P)
{
    long long row = (long long)blockIdx.x * 8 + threadIdx.y;
    float* r = P + row * T_;
    int lane = threadIdx.x;
    float4 a = *reinterpret_cast<const float4*>(&r[lane * 4]);
    float4 b = *reinterpret_cast<const float4*>(&r[128 + lane * 4]);
    float m = fmaxf(fmaxf(fmaxf(a.x, a.y), fmaxf(a.z, a.w)),
                    fmaxf(fmaxf(b.x, b.y), fmaxf(b.z, b.w)));
    #pragma unroll
    for (int o = 16; o; o >>= 1) m = fmaxf(m, __shfl_xor_sync(0xffffffffu, m, o));
    a.x = __expf(a.x - m); a.y = __expf(a.y - m); a.z = __expf(a.z - m); a.w = __expf(a.w - m);
    b.x = __expf(b.x - m); b.y = __expf(b.y - m); b.z = __expf(b.z - m); b.w = __expf(b.w - m);
    float s = a.x + a.y + a.z + a.w + b.x + b.y + b.z + b.w;
    #pragma unroll
    for (int o = 16; o; o >>= 1) s += __shfl_xor_sync(0xffffffffu, s, o);
    float inv = 1.0f / s;
    a.x *= inv; a.y *= inv; a.z *= inv; a.w *= inv;
    b.x *= inv; b.y *= inv; b.z *= inv; b.w *= inv;
    *reinterpret_cast<float4*>(&r[lane * 4]) = a;
    *reinterpret_cast<float4*>(&r[128 + lane * 4]) = b;
}

// ---------------- generic batched SGEMM: C = alpha*A@B(^T) + bias (+relu) (+resid) ----------------
#define BM 128
#define BN 64
#define BK 16

template<bool TRANSB>
__global__ void __launch_bounds__(256) gemm_kernel(
    const float* __restrict__ A, const float* __restrict__ B,
    float* __restrict__ C, const float* __restrict__ bias,
    const float* __restrict__ resid,
    int M, int N, int K, int lda, int ldb, int ldc,
    int innerB, long long sAo, long long sAi, long long sBo, long long sBi,
    long long sCo, long long sCi, float alpha, int doRelu)
{
    __shared__ float As[BK][BM + 4];
    __shared__ float Bs[BK][BN + 4];
    int z  = blockIdx.z;
    int zo = z / innerB, zi = z - zo * innerB;
    A += zo * sAo + zi * sAi;
    B += zo * sBo + zi * sBi;
    long long coff = zo * sCo + zi * sCi;
    C += coff;
    if (resid) resid += coff;

    int bm  = blockIdx.y * BM;
    int bn  = blockIdx.x * BN;
    int tid = threadIdx.x;
    int tx  = tid & 15, ty = tid >> 4;

    float acc[8][4];
    #pragma unroll
    for (int i = 0; i < 8; i++)
        #pragma unroll
        for (int j = 0; j < 4; j++) acc[i][j] = 0.f;

    for (int kt = 0; kt < K; kt += BK) {
        __syncthreads();
        // A tile: 128x16, stored transposed As[k][m]
        #pragma unroll
        for (int i = 0; i < 2; i++) {
            int e = i * 256 + tid;
            int row = e >> 2, c4 = e & 3;
            float4 va = *reinterpret_cast<const float4*>(
                &A[(long long)(bm + row) * lda + kt + c4 * 4]);
            As[c4 * 4 + 0][row] = va.x;
            As[c4 * 4 + 1][row] = va.y;
            As[c4 * 4 + 2][row] = va.z;
            As[c4 * 4 + 3][row] = va.w;
        }
        if (TRANSB) {
            // B logical [K,N] = Bmat[n, k] (row-major [N,K])
            int n = tid >> 2, c4 = tid & 3;
            float4 vb = *reinterpret_cast<const float4*>(
                &B[(long long)(bn + n) * ldb + kt + c4 * 4]);
            Bs[c4 * 4 + 0][n] = vb.x;
            Bs[c4 * 4 + 1][n] = vb.y;
            Bs[c4 * 4 + 2][n] = vb.z;
            Bs[c4 * 4 + 3][n] = vb.w;
        } else {
            int r2 = tid >> 4, c4 = tid & 15;
            float4 vb = *reinterpret_cast<const float4*>(
                &B[(long long)(kt + r2) * ldb + bn + c4 * 4]);
            *reinterpret_cast<float4*>(&Bs[r2][c4 * 4]) = vb;
        }
        __syncthreads();
        #pragma unroll
        for (int kk = 0; kk < BK; kk++) {
            float4 a0 = *reinterpret_cast<const float4*>(&As[kk][ty * 8]);
            float4 a1 = *reinterpret_cast<const float4*>(&As[kk][ty * 8 + 4]);
            float4 bv = *reinterpret_cast<const float4*>(&Bs[kk][tx * 4]);
            float av[8] = {a0.x, a0.y, a0.z, a0.w, a1.x, a1.y, a1.z, a1.w};
            float bb[4] = {bv.x, bv.y, bv.z, bv.w};
            #pragma unroll
            for (int i = 0; i < 8; i++)
                #pragma unroll
                for (int j = 0; j < 4; j++)
                    acc[i][j] += av[i] * bb[j];
        }
    }

    float4 bias4 = make_float4(0.f, 0.f, 0.f, 0.f);
    if (bias) bias4 = *reinterpret_cast<const float4*>(&bias[bn + tx * 4]);
    #pragma unroll
    for (int i = 0; i < 8; i++) {
        int row = bm + ty * 8 + i;
        float4 t;
        t.x = acc[i][0] * alpha + bias4.x;
        t.y = acc[i][1] * alpha + bias4.y;
        t.z = acc[i][2] * alpha + bias4.z;
        t.w = acc[i][3] * alpha + bias4.w;
        if (doRelu) {
            t.x = fmaxf(t.x, 0.f); t.y = fmaxf(t.y, 0.f);
            t.z = fmaxf(t.z, 0.f); t.w = fmaxf(t.w, 0.f);
        }
        if (resid) {
            float4 r = *reinterpret_cast<const float4*>(
                &resid[(long long)row * ldc + bn + tx * 4]);
            t.x += r.x; t.y += r.y; t.z += r.z; t.w += r.w;
        }
        *reinterpret_cast<float4*>(&C[(long long)row * ldc + bn + tx * 4]) = t;
    }
}

// ---------------- PVAM head: additive attention over T, one block per (m,b) ----------------
__global__ void __launch_bounds__(256) pvam_kernel(
    const float* __restrict__ wf, const float* __restrict__ emb,
    const int* __restrict__ gwp, const float* __restrict__ fc1,
    float* __restrict__ out)
{
    __shared__ float s_wp[D_];
    __shared__ float s_f[D_];
    __shared__ float s_sc[T_];
    __shared__ float s_red[32];
    int m = blockIdx.x, b = blockIdx.y;
    int tid = threadIdx.x;
    int er = gwp[m];
    for (int i = tid; i < D_; i += 256) {
        s_wp[i] = emb[(long long)er * D_ + i];
        s_f[i]  = fc1[i];
    }
    __syncthreads();

    // phase A: score[t] = sum_c tanh(wf[b,t,c] + wp[c]) * fc1[c]
    const float* wr = wf + ((long long)b * T_ + tid) * D_;
    float sc = 0.f;
    #pragma unroll 4
    for (int c4 = 0; c4 < D_ / 4; c4++) {
        float4 w = *reinterpret_cast<const float4*>(&wr[c4 * 4]);
        float4 p = *reinterpret_cast<const float4*>(&s_wp[c4 * 4]);
        float4 f = *reinterpret_cast<const float4*>(&s_f[c4 * 4]);
        sc += tanh_fast(w.x + p.x) * f.x;
        sc += tanh_fast(w.y + p.y) * f.y;
        sc += tanh_fast(w.z + p.z) * f.z;
        sc += tanh_fast(w.w + p.w) * f.w;
    }

    // block softmax over 256 scores
    int wid = tid >> 5, lane = tid & 31;
    float mv = sc;
    #pragma unroll
    for (int o = 16; o; o >>= 1) mv = fmaxf(mv, __shfl_xor_sync(0xffffffffu, mv, o));
    if (lane == 0) s_red[wid] = mv;
    __syncthreads();
    if (tid < 32) {
        float t = (tid < 8) ? s_red[tid] : -3.0e38f;
        #pragma unroll
        for (int o = 4; o; o >>= 1) t = fmaxf(t, __shfl_xor_sync(0xffffffffu, t, o));
        if (tid == 0) s_red[8] = t;
    }
    __syncthreads();
    float bmax = s_red[8];
    float e = __expf(sc - bmax);
    float sv = e;
    #pragma unroll
    for (int o = 16; o; o >>= 1) sv += __shfl_xor_sync(0xffffffffu, sv, o);
    if (lane == 0) s_red[16 + wid] = sv;
    __syncthreads();
    if (tid < 32) {
        float t = (tid < 8) ? s_red[16 + tid] : 0.f;
        #pragma unroll
        for (int o = 4; o; o >>= 1) t += __shfl_xor_sync(0xffffffffu, t, o);
        if (tid == 0) s_red[25] = t;
    }
    __syncthreads();
    float inv = 1.0f / s_red[25];
    s_sc[tid] = e * inv;
    __syncthreads();

    // phase B: out[b,m,c] = sum_t attn[t] * wf[b,t,c]
    long long base = (long long)b * T_ * D_;
    for (int c = tid; c < D_; c += 256) {
        float acc = 0.f;
        #pragma unroll 8
        for (int t = 0; t < T_; t++)
            acc += s_sc[t] * wf[base + (long long)t * D_ + c];
        out[(((long long)b * ML_) + m) * D_ + c] = acc;
    }
}

// ---------------- host launcher ----------------
static inline void run_gemm(bool transb, const float* A, const float* Bm, float* C,
                            const float* bias, const float* resid,
                            int M, int N, int K, int lda, int ldb, int ldc,
                            int innerB, long long sAo, long long sAi,
                            long long sBo, long long sBi, long long sCo, long long sCi,
                            float alpha, int doRelu, int batch)
{
    dim3 grid(N / BN, M / BM, batch), block(256);
    if (transb)
        gemm_kernel<true><<<grid, block>>>(A, Bm, C, bias, resid, M, N, K, lda, ldb, ldc,
                                           innerB, sAo, sAi, sBo, sBi, sCo, sCi, alpha, doRelu);
    else
        gemm_kernel<false><<<grid, block>>>(A, Bm, C, bias, resid, M, N, K, lda, ldb, ldc,
                                            innerB, sAo, sAi, sBo, sBi, sCo, sCi, alpha, doRelu);
}

extern "C" void kernel_launch(void* const* d_in, const int* in_sizes, int n_in,
                              void* d_out, int out_size)
{
    const float* x    = (const float*)d_in[0];
    const int*   ewp  = (const int*)  d_in[1];
    const int*   gwp  = (const int*)  d_in[2];
    const float* pos  = (const float*)d_in[3];
    const float* ln1s = (const float*)d_in[4];
    const float* ln1b = (const float*)d_in[5];
    const float* Wq   = (const float*)d_in[6];
    const float* bq   = (const float*)d_in[7];
    const float* Wk   = (const float*)d_in[8];
    const float* bk   = (const float*)d_in[9];
    const float* Wv   = (const float*)d_in[10];
    const float* bv   = (const float*)d_in[11];
    const float* Wo   = (const float*)d_in[12];
    const float* bo   = (const float*)d_in[13];
    const float* ln2s = (const float*)d_in[14];
    const float* ln2b = (const float*)d_in[15];
    const float* W1   = (const float*)d_in[16];
    const float* b1   = (const float*)d_in[17];
    const float* W2   = (const float*)d_in[18];
    const float* b2   = (const float*)d_in[19];
    const float* lnfs = (const float*)d_in[20];
    const float* lnfb = (const float*)d_in[21];
    const float* fc0w = (const float*)d_in[22];
    const float* fc0b = (const float*)d_in[23];
    const float* emb  = (const float*)d_in[24];
    const float* fc1  = (const float*)d_in[25];

    static float *enc = nullptr, *tmp, *q, *k, *v, *o, *p;
    if (!enc) {  // deterministic: same pointers every call; no API calls during capture
        cudaGetSymbolAddress((void**)&enc, g_enc);
        cudaGetSymbolAddress((void**)&tmp, g_tmp);
        cudaGetSymbolAddress((void**)&q,   g_q);
        cudaGetSymbolAddress((void**)&k,   g_k);
        cudaGetSymbolAddress((void**)&v,   g_v);
        cudaGetSymbolAddress((void**)&o,   g_o);
        cudaGetSymbolAddress((void**)&p,   g_p);
    }

    prep_kernel<<<dim3(D_ / 32, T_ / 32, B_), dim3(32, 8)>>>(x, pos, ewp, enc);

    const int MT = B_ * T_;  // 8192
    for (int l = 0; l < L_; l++) {
        long long wo = (long long)l * D_ * D_;
        int vo = l * D_;

        ln_kernel<<<MT / 8, dim3(32, 8)>>>(enc, tmp, ln1s + vo, ln1b + vo);
        run_gemm(false, tmp, Wq + wo, q, bq + vo, nullptr, MT, D_, D_, D_, D_, D_,
                 1, 0, 0, 0, 0, 0, 0, 1.f, 0, 1);
        run_gemm(false, tmp, Wk + wo, k, bk + vo, nullptr, MT, D_, D_, D_, D_, D_,
                 1, 0, 0, 0, 0, 0, 0, 1.f, 0, 1);
        run_gemm(false, tmp, Wv + wo, v, bv + vo, nullptr, MT, D_, D_, D_, D_, D_,
                 1, 0, 0, 0, 0, 0, 0, 1.f, 0, 1);

        // S = (Q K^T) * 1/sqrt(dk), batched over (b,h)
        run_gemm(true, q, k, p, nullptr, nullptr, T_, T_, DK_, D_, D_, T_,
                 NH_, (long long)T_ * D_, DK_, (long long)T_ * D_, DK_,
                 (long long)NH_ * T_ * T_, (long long)T_ * T_, 0.125f, 0, B_ * NH_);
        softmax_kernel<<<(B_ * NH_ * T_) / 8, dim3(32, 8)>>>(p);
        // O = P V, batched over (b,h)
        run_gemm(false, p, v, o, nullptr, nullptr, T_, DK_, T_, T_, D_, D_,
                 NH_, (long long)NH_ * T_ * T_, (long long)T_ * T_,
                 (long long)T_ * D_, DK_, (long long)T_ * D_, DK_, 1.f, 0, B_ * NH_);

        run_gemm(false, o, Wo + wo, enc, bo + vo, enc, MT, D_, D_, D_, D_, D_,
                 1, 0, 0, 0, 0, 0, 0, 1.f, 0, 1);

        ln_kernel<<<MT / 8, dim3(32, 8)>>>(enc, tmp, ln2s + vo, ln2b + vo);
        run_gemm(false, tmp, W1 + wo, o, b1 + vo, nullptr, MT, D_, D_, D_, D_, D_,
                 1, 0, 0, 0, 0, 0, 0, 1.f, 1, 1);
        run_gemm(false, o, W2 + wo, enc, b2 + vo, enc, MT, D_, D_, D_, D_, D_,
                 1, 0, 0, 0, 0, 0, 0, 1.f, 0, 1);
    }

    ln_kernel<<<MT / 8, dim3(32, 8)>>>(enc, tmp, lnfs, lnfb);
    run_gemm(false, tmp, fc0w, q, fc0b, nullptr, MT, D_, D_, D_, D_, D_,
             1, 0, 0, 0, 0, 0, 0, 1.f, 0, 1);  // q := word_features

    pvam_kernel<<<dim3(ML_, B_), 256>>>(q, emb, gwp, fc1, (float*)d_out);
}

// round 3
// speedup vs baseline: 1.7314x; 1.7314x over previous
#include <cuda_runtime.h>
#include <math.h>

// ---------------- problem constants ----------------
#define B_  32
#define T_  256
#define D_  512
#define NH_ 8
#define DK_ 64
#define L_  2
#define ML_ 25
#define NWMAT 13

// ---------------- scratch (device globals; no allocation allowed) ----------------
__device__ float g_enc[B_*T_*D_];
__device__ float g_tmp[B_*T_*D_];
__device__ float g_q  [B_*T_*D_];
__device__ float g_k  [B_*T_*D_];
__device__ float g_v  [B_*T_*D_];
__device__ float g_o  [B_*T_*D_];
__device__ float g_p  [B_*NH_*T_*T_];
__device__ float g_wT [NWMAT*D_*D_];   // transposed (K-major) weights

__device__ __forceinline__ unsigned f2tf32(float x) {
    unsigned r;
    asm("cvt.rna.tf32.f32 %0, %1;" : "=r"(r) : "f"(x));
    return r;
}
__device__ __forceinline__ float tanh_fast(float x) {
    float y;
    asm("tanh.approx.f32 %0, %1;" : "=f"(y) : "f"(x));
    return y;
}

// ---------------- prep: enc[b,t,d] = x[b,d,t]*sqrt(D) + pos[ewp[t], d] ----------------
__global__ void prep_kernel(const float* __restrict__ x, const float* __restrict__ pos,
                            const int* __restrict__ ewp, float* __restrict__ enc)
{
    __shared__ float tile[32][33];
    int b  = blockIdx.z;
    int d0 = blockIdx.x * 32, t0 = blockIdx.y * 32;
    int tx = threadIdx.x, ty = threadIdx.y;
    const float* xb = x + (long long)b * D_ * T_;
    #pragma unroll
    for (int i = 0; i < 4; i++) {
        int d = ty + i * 8;
        tile[d][tx] = xb[(long long)(d0 + d) * T_ + t0 + tx];
    }
    __syncthreads();
    #pragma unroll
    for (int i = 0; i < 4; i++) {
        int tl = ty + i * 8;
        int t = t0 + tl, d = d0 + tx;
        int pr = ewp[t];
        enc[(((long long)b * T_) + t) * D_ + d] =
            tile[tx][tl] * 22.62741699796952f + pos[(long long)pr * D_ + d];
    }
}

// ---------------- weight transpose: wT[n][k] = W[k][n] ----------------
struct WP { const float* w[NWMAT]; };
__global__ void wtrans_kernel(WP p, float* __restrict__ out)
{
    __shared__ float t[32][33];
    int mi = blockIdx.z;
    const float* W = p.w[mi];
    float* O = out + (long long)mi * D_ * D_;
    int n0 = blockIdx.x * 32, k0 = blockIdx.y * 32;
    int tx = threadIdx.x, ty = threadIdx.y;
    #pragma unroll
    for (int i = 0; i < 4; i++) {
        int k = k0 + ty + i * 8;
        t[ty + i * 8][tx] = W[(long long)k * D_ + n0 + tx];
    }
    __syncthreads();
    #pragma unroll
    for (int i = 0; i < 4; i++) {
        int n = n0 + ty + i * 8;
        O[(long long)n * D_ + k0 + tx] = t[tx][ty + i * 8];
    }
}

// ---------------- layernorm over D=512, one warp per row ----------------
__global__ void ln_kernel(const float* __restrict__ in, float* __restrict__ out,
                          const float* __restrict__ gs, const float* __restrict__ gb)
{
    int row  = blockIdx.x * 8 + threadIdx.y;
    int lane = threadIdx.x;
    const float* r = in + (long long)row * D_;
    float4 xv[4];
    #pragma unroll
    for (int j = 0; j < 4; j++)
        xv[j] = *reinterpret_cast<const float4*>(&r[(j * 32 + lane) * 4]);
    float s = 0.f;
    #pragma unroll
    for (int j = 0; j < 4; j++) s += xv[j].x + xv[j].y + xv[j].z + xv[j].w;
    #pragma unroll
    for (int o = 16; o; o >>= 1) s += __shfl_xor_sync(0xffffffffu, s, o);
    float mean = s * (1.0f / D_);
    float vs = 0.f;
    #pragma unroll
    for (int j = 0; j < 4; j++) {
        float a = xv[j].x - mean, b2 = xv[j].y - mean, c = xv[j].z - mean, d = xv[j].w - mean;
        vs += a * a + b2 * b2 + c * c + d * d;
    }
    #pragma unroll
    for (int o = 16; o; o >>= 1) vs += __shfl_xor_sync(0xffffffffu, vs, o);
    float rstd = rsqrtf(vs * (1.0f / D_) + 1e-5f);
    float* w = out + (long long)row * D_;
    #pragma unroll
    for (int j = 0; j < 4; j++) {
        int c0 = (j * 32 + lane) * 4;
        float4 sv = *reinterpret_cast<const float4*>(&gs[c0]);
        float4 bv = *reinterpret_cast<const float4*>(&gb[c0]);
        float4 t;
        t.x = (xv[j].x - mean) * rstd * sv.x + bv.x;
        t.y = (xv[j].y - mean) * rstd * sv.y + bv.y;
        t.z = (xv[j].z - mean) * rstd * sv.z + bv.z;
        t.w = (xv[j].w - mean) * rstd * sv.w + bv.w;
        *reinterpret_cast<float4*>(&w[c0]) = t;
    }
}

// ---------------- softmax over rows of length 256 ----------------
__global__ void softmax_kernel(float* __restrict__ P)
{
    long long row = (long long)blockIdx.x * 8 + threadIdx.y;
    float* r = P + row * T_;
    int lane = threadIdx.x;
    float4 a = *reinterpret_cast<const float4*>(&r[lane * 4]);
    float4 b = *reinterpret_cast<const float4*>(&r[128 + lane * 4]);
    float m = fmaxf(fmaxf(fmaxf(a.x, a.y), fmaxf(a.z, a.w)),
                    fmaxf(fmaxf(b.x, b.y), fmaxf(b.z, b.w)));
    #pragma unroll
    for (int o = 16; o; o >>= 1) m = fmaxf(m, __shfl_xor_sync(0xffffffffu, m, o));
    a.x = __expf(a.x - m); a.y = __expf(a.y - m); a.z = __expf(a.z - m); a.w = __expf(a.w - m);
    b.x = __expf(b.x - m); b.y = __expf(b.y - m); b.z = __expf(b.z - m); b.w = __expf(b.w - m);
    float s = a.x + a.y + a.z + a.w + b.x + b.y + b.z + b.w;
    #pragma unroll
    for (int o = 16; o; o >>= 1) s += __shfl_xor_sync(0xffffffffu, s, o);
    float inv = 1.0f / s;
    a.x *= inv; a.y *= inv; a.z *= inv; a.w *= inv;
    b.x *= inv; b.y *= inv; b.z *= inv; b.w *= inv;
    *reinterpret_cast<float4*>(&r[lane * 4]) = a;
    *reinterpret_cast<float4*>(&r[128 + lane * 4]) = b;
}

// ======================================================================
// mma.sync tf32 GEMM: C[8192,512] = A[8192,512] @ Bt[512,512]^T
//   (+bias)(+relu)(+resid).   Bt is K-major: Bt[n][k].
// CTA tile 128x64, BK=32, 8 warps of 32x32 each (m16n8k8 fragments).
// ======================================================================
#define TGM 128
#define TGN 64
#define TBK 32
#define TSTR 36   // smem row stride in floats (pad vs 32 for bank spread)

__device__ __forceinline__ void mma_tf32(float c[4],
                                         unsigned a0, unsigned a1, unsigned a2, unsigned a3,
                                         unsigned b0, unsigned b1)
{
    asm volatile(
        "mma.sync.aligned.m16n8k8.row.col.f32.tf32.tf32.f32 "
        "{%0,%1,%2,%3}, {%4,%5,%6,%7}, {%8,%9}, {%0,%1,%2,%3};"
        : "+f"(c[0]), "+f"(c[1]), "+f"(c[2]), "+f"(c[3])
        : "r"(a0), "r"(a1), "r"(a2), "r"(a3), "r"(b0), "r"(b1));
}

__global__ void __launch_bounds__(256) tgemm_kernel(
    const float* __restrict__ A, const float* __restrict__ Bt,
    float* __restrict__ C, const float* __restrict__ bias,
    const float* __restrict__ resid, int doRelu)
{
    __shared__ unsigned As[TGM * TSTR];
    __shared__ unsigned Bs[TGN * TSTR];

    int tid  = threadIdx.x;
    int w    = tid >> 5, lane = tid & 31;
    int g    = lane >> 2, tig = lane & 3;
    int bm   = blockIdx.y * TGM, bn = blockIdx.x * TGN;
    int wm   = (w & 3) * 32;        // warp M offset within CTA tile
    int wn   = (w >> 2) * 32;       // warp N offset

    float acc[2][4][4];
    #pragma unroll
    for (int i = 0; i < 2; i++)
        #pragma unroll
        for (int j = 0; j < 4; j++)
            #pragma unroll
            for (int q = 0; q < 4; q++) acc[i][j][q] = 0.f;

    for (int kt = 0; kt < D_; kt += TBK) {
        __syncthreads();
        // A tile 128x32 -> As[m*36 + k], tf32-rounded
        #pragma unroll
        for (int i = 0; i < 4; i++) {
            int idx = tid + i * 256;
            int row = idx >> 3, kc = idx & 7;
            float4 v = *reinterpret_cast<const float4*>(
                &A[(long long)(bm + row) * D_ + kt + kc * 4]);
            uint4 u = make_uint4(f2tf32(v.x), f2tf32(v.y), f2tf32(v.z), f2tf32(v.w));
            *reinterpret_cast<uint4*>(&As[row * TSTR + kc * 4]) = u;
        }
        // B tile 64x32 (K-major rows) -> Bs[n*36 + k]
        #pragma unroll
        for (int i = 0; i < 2; i++) {
            int idx = tid + i * 256;
            int row = idx >> 3, kc = idx & 7;
            float4 v = *reinterpret_cast<const float4*>(
                &Bt[(long long)(bn + row) * D_ + kt + kc * 4]);
            uint4 u = make_uint4(f2tf32(v.x), f2tf32(v.y), f2tf32(v.z), f2tf32(v.w));
            *reinterpret_cast<uint4*>(&Bs[row * TSTR + kc * 4]) = u;
        }
        __syncthreads();

        #pragma unroll
        for (int ks = 0; ks < TBK / 8; ks++) {
            int k0 = ks * 8;
            unsigned af[2][4], bf[4][2];
            #pragma unroll
            for (int mt = 0; mt < 2; mt++) {
                int r0 = wm + mt * 16;
                af[mt][0] = As[(r0 + g)     * TSTR + k0 + tig];
                af[mt][1] = As[(r0 + 8 + g) * TSTR + k0 + tig];
                af[mt][2] = As[(r0 + g)     * TSTR + k0 + tig + 4];
                af[mt][3] = As[(r0 + 8 + g) * TSTR + k0 + tig + 4];
            }
            #pragma unroll
            for (int nt = 0; nt < 4; nt++) {
                int n0 = wn + nt * 8;
                bf[nt][0] = Bs[(n0 + g) * TSTR + k0 + tig];
                bf[nt][1] = Bs[(n0 + g) * TSTR + k0 + tig + 4];
            }
            #pragma unroll
            for (int mt = 0; mt < 2; mt++)
                #pragma unroll
                for (int nt = 0; nt < 4; nt++)
                    mma_tf32(acc[mt][nt], af[mt][0], af[mt][1], af[mt][2], af[mt][3],
                             bf[nt][0], bf[nt][1]);
        }
    }

    // epilogue: c0,c1 -> (row, col..col+1), c2,c3 -> (row+8, ...)
    #pragma unroll
    for (int mt = 0; mt < 2; mt++) {
        #pragma unroll
        for (int nt = 0; nt < 4; nt++) {
            int row0 = bm + wm + mt * 16 + g;
            int col  = bn + wn + nt * 8 + 2 * tig;
            float2 bv = *reinterpret_cast<const float2*>(&bias[col]);
            float2 t0 = make_float2(acc[mt][nt][0] + bv.x, acc[mt][nt][1] + bv.y);
            float2 t1 = make_float2(acc[mt][nt][2] + bv.x, acc[mt][nt][3] + bv.y);
            if (doRelu) {
                t0.x = fmaxf(t0.x, 0.f); t0.y = fmaxf(t0.y, 0.f);
                t1.x = fmaxf(t1.x, 0.f); t1.y = fmaxf(t1.y, 0.f);
            }
            if (resid) {
                float2 r0 = *reinterpret_cast<const float2*>(
                    &resid[(long long)row0 * D_ + col]);
                float2 r1 = *reinterpret_cast<const float2*>(
                    &resid[(long long)(row0 + 8) * D_ + col]);
                t0.x += r0.x; t0.y += r0.y;
                t1.x += r1.x; t1.y += r1.y;
            }
            *reinterpret_cast<float2*>(&C[(long long)row0 * D_ + col]) = t0;
            *reinterpret_cast<float2*>(&C[(long long)(row0 + 8) * D_ + col]) = t1;
        }
    }
}

// ---------------- scalar batched SGEMM (attention only) ----------------
#define BM 128
#define BN 64
#define BK 16

template<bool TRANSB>
__global__ void __launch_bounds__(256) gemm_kernel(
    const float* __restrict__ A, const float* __restrict__ B,
    float* __restrict__ C,
    int M, int N, int K, int lda, int ldb, int ldc,
    int innerB, long long sAo, long long sAi, long long sBo, long long sBi,
    long long sCo, long long sCi, float alpha)
{
    __shared__ float As[BK][BM + 4];
    __shared__ float Bs[BK][BN + 4];
    int z  = blockIdx.z;
    int zo = z / innerB, zi = z - zo * innerB;
    A += zo * sAo + zi * sAi;
    B += zo * sBo + zi * sBi;
    C += zo * sCo + zi * sCi;

    int bm  = blockIdx.y * BM;
    int bn  = blockIdx.x * BN;
    int tid = threadIdx.x;
    int tx  = tid & 15, ty = tid >> 4;

    float acc[8][4];
    #pragma unroll
    for (int i = 0; i < 8; i++)
        #pragma unroll
        for (int j = 0; j < 4; j++) acc[i][j] = 0.f;

    for (int kt = 0; kt < K; kt += BK) {
        __syncthreads();
        #pragma unroll
        for (int i = 0; i < 2; i++) {
            int e = i * 256 + tid;
            int row = e >> 2, c4 = e & 3;
            float4 va = *reinterpret_cast<const float4*>(
                &A[(long long)(bm + row) * lda + kt + c4 * 4]);
            As[c4 * 4 + 0][row] = va.x;
            As[c4 * 4 + 1][row] = va.y;
            As[c4 * 4 + 2][row] = va.z;
            As[c4 * 4 + 3][row] = va.w;
        }
        if (TRANSB) {
            int n = tid >> 2, c4 = tid & 3;
            float4 vb = *reinterpret_cast<const float4*>(
                &B[(long long)(bn + n) * ldb + kt + c4 * 4]);
            Bs[c4 * 4 + 0][n] = vb.x;
            Bs[c4 * 4 + 1][n] = vb.y;
            Bs[c4 * 4 + 2][n] = vb.z;
            Bs[c4 * 4 + 3][n] = vb.w;
        } else {
            int r2 = tid >> 4, c4 = tid & 15;
            float4 vb = *reinterpret_cast<const float4*>(
                &B[(long long)(kt + r2) * ldb + bn + c4 * 4]);
            *reinterpret_cast<float4*>(&Bs[r2][c4 * 4]) = vb;
        }
        __syncthreads();
        #pragma unroll
        for (int kk = 0; kk < BK; kk++) {
            float4 a0 = *reinterpret_cast<const float4*>(&As[kk][ty * 8]);
            float4 a1 = *reinterpret_cast<const float4*>(&As[kk][ty * 8 + 4]);
            float4 bv = *reinterpret_cast<const float4*>(&Bs[kk][tx * 4]);
            float av[8] = {a0.x, a0.y, a0.z, a0.w, a1.x, a1.y, a1.z, a1.w};
            float bb[4] = {bv.x, bv.y, bv.z, bv.w};
            #pragma unroll
            for (int i = 0; i < 8; i++)
                #pragma unroll
                for (int j = 0; j < 4; j++)
                    acc[i][j] += av[i] * bb[j];
        }
    }

    #pragma unroll
    for (int i = 0; i < 8; i++) {
        int row = bm + ty * 8 + i;
        float4 t;
        t.x = acc[i][0] * alpha;
        t.y = acc[i][1] * alpha;
        t.z = acc[i][2] * alpha;
        t.w = acc[i][3] * alpha;
        *reinterpret_cast<float4*>(&C[(long long)row * ldc + bn + tx * 4]) = t;
    }
}

// ---------------- PVAM head ----------------
__global__ void __launch_bounds__(256) pvam_kernel(
    const float* __restrict__ wf, const float* __restrict__ emb,
    const int* __restrict__ gwp, const float* __restrict__ fc1,
    float* __restrict__ out)
{
    __shared__ float s_wp[D_];
    __shared__ float s_f[D_];
    __shared__ float s_sc[T_];
    __shared__ float s_red[32];
    int m = blockIdx.x, b = blockIdx.y;
    int tid = threadIdx.x;
    int er = gwp[m];
    for (int i = tid; i < D_; i += 256) {
        s_wp[i] = emb[(long long)er * D_ + i];
        s_f[i]  = fc1[i];
    }
    __syncthreads();

    const float* wr = wf + ((long long)b * T_ + tid) * D_;
    float sc = 0.f;
    #pragma unroll 4
    for (int c4 = 0; c4 < D_ / 4; c4++) {
        float4 w = *reinterpret_cast<const float4*>(&wr[c4 * 4]);
        float4 p = *reinterpret_cast<const float4*>(&s_wp[c4 * 4]);
        float4 f = *reinterpret_cast<const float4*>(&s_f[c4 * 4]);
        sc += tanh_fast(w.x + p.x) * f.x;
        sc += tanh_fast(w.y + p.y) * f.y;
        sc += tanh_fast(w.z + p.z) * f.z;
        sc += tanh_fast(w.w + p.w) * f.w;
    }

    int wid = tid >> 5, lane = tid & 31;
    float mv = sc;
    #pragma unroll
    for (int o = 16; o; o >>= 1) mv = fmaxf(mv, __shfl_xor_sync(0xffffffffu, mv, o));
    if (lane == 0) s_red[wid] = mv;
    __syncthreads();
    if (tid < 32) {
        float t = (tid < 8) ? s_red[tid] : -3.0e38f;
        #pragma unroll
        for (int o = 4; o; o >>= 1) t = fmaxf(t, __shfl_xor_sync(0xffffffffu, t, o));
        if (tid == 0) s_red[8] = t;
    }
    __syncthreads();
    float bmax = s_red[8];
    float e = __expf(sc - bmax);
    float sv = e;
    #pragma unroll
    for (int o = 16; o; o >>= 1) sv += __shfl_xor_sync(0xffffffffu, sv, o);
    if (lane == 0) s_red[16 + wid] = sv;
    __syncthreads();
    if (tid < 32) {
        float t = (tid < 8) ? s_red[16 + tid] : 0.f;
        #pragma unroll
        for (int o = 4; o; o >>= 1) t += __shfl_xor_sync(0xffffffffu, t, o);
        if (tid == 0) s_red[25] = t;
    }
    __syncthreads();
    float inv = 1.0f / s_red[25];
    s_sc[tid] = e * inv;
    __syncthreads();

    long long base = (long long)b * T_ * D_;
    for (int c = tid; c < D_; c += 256) {
        float acc = 0.f;
        #pragma unroll 8
        for (int t = 0; t < T_; t++)
            acc += s_sc[t] * wf[base + (long long)t * D_ + c];
        out[(((long long)b * ML_) + m) * D_ + c] = acc;
    }
}

// ---------------- host launcher ----------------
extern "C" void kernel_launch(void* const* d_in, const int* in_sizes, int n_in,
                              void* d_out, int out_size)
{
    const float* x    = (const float*)d_in[0];
    const int*   ewp  = (const int*)  d_in[1];
    const int*   gwp  = (const int*)  d_in[2];
    const float* pos  = (const float*)d_in[3];
    const float* ln1s = (const float*)d_in[4];
    const float* ln1b = (const float*)d_in[5];
    const float* Wq   = (const float*)d_in[6];
    const float* bq   = (const float*)d_in[7];
    const float* Wk   = (const float*)d_in[8];
    const float* bk   = (const float*)d_in[9];
    const float* Wv   = (const float*)d_in[10];
    const float* bv   = (const float*)d_in[11];
    const float* Wo   = (const float*)d_in[12];
    const float* bo   = (const float*)d_in[13];
    const float* ln2s = (const float*)d_in[14];
    const float* ln2b = (const float*)d_in[15];
    const float* W1   = (const float*)d_in[16];
    const float* b1   = (const float*)d_in[17];
    const float* W2   = (const float*)d_in[18];
    const float* b2   = (const float*)d_in[19];
    const float* lnfs = (const float*)d_in[20];
    const float* lnfb = (const float*)d_in[21];
    const float* fc0w = (const float*)d_in[22];
    const float* fc0b = (const float*)d_in[23];
    const float* emb  = (const float*)d_in[24];
    const float* fc1  = (const float*)d_in[25];

    static float *enc = nullptr, *tmp, *q, *k, *v, *o, *p, *wT;
    if (!enc) {
        cudaGetSymbolAddress((void**)&enc, g_enc);
        cudaGetSymbolAddress((void**)&tmp, g_tmp);
        cudaGetSymbolAddress((void**)&q,   g_q);
        cudaGetSymbolAddress((void**)&k,   g_k);
        cudaGetSymbolAddress((void**)&v,   g_v);
        cudaGetSymbolAddress((void**)&o,   g_o);
        cudaGetSymbolAddress((void**)&p,   g_p);
        cudaGetSymbolAddress((void**)&wT,  g_wT);
    }

    const long long DD = (long long)D_ * D_;

    // transpose all 13 weight matrices into K-major scratch
    WP wp;
    wp.w[0]  = Wq;       wp.w[1]  = Wk;       wp.w[2]  = Wv;
    wp.w[3]  = Wo;       wp.w[4]  = W1;       wp.w[5]  = W2;
    wp.w[6]  = Wq + DD;  wp.w[7]  = Wk + DD;  wp.w[8]  = Wv + DD;
    wp.w[9]  = Wo + DD;  wp.w[10] = W1 + DD;  wp.w[11] = W2 + DD;
    wp.w[12] = fc0w;
    wtrans_kernel<<<dim3(16, 16, NWMAT), dim3(32, 8)>>>(wp, wT);

    prep_kernel<<<dim3(D_ / 32, T_ / 32, B_), dim3(32, 8)>>>(x, pos, ewp, enc);

    const int MT = B_ * T_;   // 8192
    const dim3 tg(D_ / TGN, MT / TGM);  // (8, 64)

    for (int l = 0; l < L_; l++) {
        int vo = l * D_;
        const float* wq = wT + (l * 6 + 0) * DD;
        const float* wk = wT + (l * 6 + 1) * DD;
        const float* wv = wT + (l * 6 + 2) * DD;
        const float* wo = wT + (l * 6 + 3) * DD;
        const float* w1 = wT + (l * 6 + 4) * DD;
        const float* w2 = wT + (l * 6 + 5) * DD;

        ln_kernel<<<MT / 8, dim3(32, 8)>>>(enc, tmp, ln1s + vo, ln1b + vo);
        tgemm_kernel<<<tg, 256>>>(tmp, wq, q, bq + vo, nullptr, 0);
        tgemm_kernel<<<tg, 256>>>(tmp, wk, k, bk + vo, nullptr, 0);
        tgemm_kernel<<<tg, 256>>>(tmp, wv, v, bv + vo, nullptr, 0);

        // S = (Q K^T) / sqrt(dk), batched over (b,h)
        gemm_kernel<true><<<dim3(T_ / BN, T_ / BM, B_ * NH_), 256>>>(
            q, k, p, T_, T_, DK_, D_, D_, T_,
            NH_, (long long)T_ * D_, DK_, (long long)T_ * D_, DK_,
            (long long)NH_ * T_ * T_, (long long)T_ * T_, 0.125f);
        softmax_kernel<<<(B_ * NH_ * T_) / 8, dim3(32, 8)>>>(p);
        // O = P V, batched over (b,h)
        gemm_kernel<false><<<dim3(DK_ / BN, T_ / BM, B_ * NH_), 256>>>(
            p, v, o, T_, DK_, T_, T_, D_, D_,
            NH_, (long long)NH_ * T_ * T_, (long long)T_ * T_,
            (long long)T_ * D_, DK_, (long long)T_ * D_, DK_, 1.f);

        tgemm_kernel<<<tg, 256>>>(o, wo, enc, bo + vo, enc, 0);

        ln_kernel<<<MT / 8, dim3(32, 8)>>>(enc, tmp, ln2s + vo, ln2b + vo);
        tgemm_kernel<<<tg, 256>>>(tmp, w1, o, b1 + vo, nullptr, 1);
        tgemm_kernel<<<tg, 256>>>(o, w2, enc, b2 + vo, enc, 0);
    }

    ln_kernel<<<MT / 8, dim3(32, 8)>>>(enc, tmp, lnfs, lnfb);
    tgemm_kernel<<<tg, 256>>>(tmp, wT + 12 * DD, q, fc0b, nullptr, 0);  // q := word_features

    pvam_kernel<<<dim3(ML_, B_), 256>>>(q, emb, gwp, fc1, (float*)d_out);
}

// round 4
// speedup vs baseline: 1.8104x; 1.0457x over previous
#include <cuda_runtime.h>
#include <math.h>

// ---------------- problem constants ----------------
#define B_  32
#define T_  256
#define D_  512
#define NH_ 8
#define DK_ 64
#define L_  2
#define ML_ 25
#define NWMAT 13

// ---------------- scratch (device globals; no allocation allowed) ----------------
__device__ float g_enc[B_*T_*D_];
__device__ float g_tmp[B_*T_*D_];
__device__ float g_q  [B_*T_*D_];
__device__ float g_k  [B_*T_*D_];
__device__ float g_v  [B_*T_*D_];
__device__ float g_o  [B_*T_*D_];
__device__ float g_p  [B_*NH_*T_*T_];
__device__ float g_wT [NWMAT*D_*D_];   // transposed, tf32-rounded, k-permuted weights

__device__ __forceinline__ unsigned f2tf32(float x) {
    unsigned r;
    asm("cvt.rna.tf32.f32 %0, %1;" : "=r"(r) : "f"(x));
    return r;
}
__device__ __forceinline__ float rndtf(float v) { return __uint_as_float(f2tf32(v)); }
__device__ __forceinline__ float tanh_fast(float x) {
    float y;
    asm("tanh.approx.f32 %0, %1;" : "=f"(y) : "f"(x));
    return y;
}
// permuted scalar store: value of logical column c goes to block-base + (c&3)*8 + ((c&31)>>2)
__device__ __forceinline__ void st_perm(float* rowp, int c, float v) {
    rowp[(c & ~31) + (c & 3) * 8 + ((c & 31) >> 2)] = rndtf(v);
}

#define CP16(dst, src) \
    asm volatile("cp.async.cg.shared.global [%0], [%1], 16;" :: "r"(dst), "l"(src) : "memory")

// ---------------- prep: enc[b,t,d] = x[b,d,t]*sqrt(D) + pos[ewp[t], d] ----------------
__global__ void prep_kernel(const float* __restrict__ x, const float* __restrict__ pos,
                            const int* __restrict__ ewp, float* __restrict__ enc)
{
    __shared__ float tile[32][33];
    int b  = blockIdx.z;
    int d0 = blockIdx.x * 32, t0 = blockIdx.y * 32;
    int tx = threadIdx.x, ty = threadIdx.y;
    const float* xb = x + (long long)b * D_ * T_;
    #pragma unroll
    for (int i = 0; i < 4; i++) {
        int d = ty + i * 8;
        tile[d][tx] = xb[(long long)(d0 + d) * T_ + t0 + tx];
    }
    __syncthreads();
    #pragma unroll
    for (int i = 0; i < 4; i++) {
        int tl = ty + i * 8;
        int t = t0 + tl, d = d0 + tx;
        int pr = ewp[t];
        enc[(((long long)b * T_) + t) * D_ + d] =
            tile[tx][tl] * 22.62741699796952f + pos[(long long)pr * D_ + d];
    }
}

// ---------------- weight transpose: wT[n][perm(k)] = round(W[k][n]) ----------------
struct WP { const float* w[NWMAT]; };
__global__ void wtrans_kernel(WP p, float* __restrict__ out)
{
    __shared__ float t[32][33];
    int mi = blockIdx.z;
    const float* W = p.w[mi];
    float* O = out + (long long)mi * D_ * D_;
    int n0 = blockIdx.x * 32, k0 = blockIdx.y * 32;
    int tx = threadIdx.x, ty = threadIdx.y;
    #pragma unroll
    for (int i = 0; i < 4; i++) {
        int k = k0 + ty + i * 8;
        t[ty + i * 8][tx] = W[(long long)k * D_ + n0 + tx];
    }
    __syncthreads();
    #pragma unroll
    for (int i = 0; i < 4; i++) {
        int n = n0 + ty + i * 8;
        O[(long long)n * D_ + k0 + (tx & 3) * 8 + (tx >> 2)] = rndtf(t[tx][ty + i * 8]);
    }
}

// ---------------- layernorm over D=512 (output tf32-rounded + k-permuted) ----------------
__global__ void ln_kernel(const float* __restrict__ in, float* __restrict__ out,
                          const float* __restrict__ gs, const float* __restrict__ gb)
{
    int row  = blockIdx.x * 8 + threadIdx.y;
    int lane = threadIdx.x;
    const float* r = in + (long long)row * D_;
    float4 xv[4];
    #pragma unroll
    for (int j = 0; j < 4; j++)
        xv[j] = *reinterpret_cast<const float4*>(&r[(j * 32 + lane) * 4]);
    float s = 0.f;
    #pragma unroll
    for (int j = 0; j < 4; j++) s += xv[j].x + xv[j].y + xv[j].z + xv[j].w;
    #pragma unroll
    for (int o = 16; o; o >>= 1) s += __shfl_xor_sync(0xffffffffu, s, o);
    float mean = s * (1.0f / D_);
    float vs = 0.f;
    #pragma unroll
    for (int j = 0; j < 4; j++) {
        float a = xv[j].x - mean, b2 = xv[j].y - mean, c = xv[j].z - mean, d = xv[j].w - mean;
        vs += a * a + b2 * b2 + c * c + d * d;
    }
    #pragma unroll
    for (int o = 16; o; o >>= 1) vs += __shfl_xor_sync(0xffffffffu, vs, o);
    float rstd = rsqrtf(vs * (1.0f / D_) + 1e-5f);
    float* w = out + (long long)row * D_;
    #pragma unroll
    for (int j = 0; j < 4; j++) {
        int c0 = (j * 32 + lane) * 4;
        float4 sv = *reinterpret_cast<const float4*>(&gs[c0]);
        float4 bv = *reinterpret_cast<const float4*>(&gb[c0]);
        float tx = (xv[j].x - mean) * rstd * sv.x + bv.x;
        float ty = (xv[j].y - mean) * rstd * sv.y + bv.y;
        float tz = (xv[j].z - mean) * rstd * sv.z + bv.z;
        float tw = (xv[j].w - mean) * rstd * sv.w + bv.w;
        float* wp = w + (c0 & ~31);
        int qq = (c0 & 31) >> 2;
        wp[qq]      = rndtf(tx);
        wp[8 + qq]  = rndtf(ty);
        wp[16 + qq] = rndtf(tz);
        wp[24 + qq] = rndtf(tw);
    }
}

// ---------------- softmax over rows of length 256 ----------------
__global__ void softmax_kernel(float* __restrict__ P)
{
    long long row = (long long)blockIdx.x * 8 + threadIdx.y;
    float* r = P + row * T_;
    int lane = threadIdx.x;
    float4 a = *reinterpret_cast<const float4*>(&r[lane * 4]);
    float4 b = *reinterpret_cast<const float4*>(&r[128 + lane * 4]);
    float m = fmaxf(fmaxf(fmaxf(a.x, a.y), fmaxf(a.z, a.w)),
                    fmaxf(fmaxf(b.x, b.y), fmaxf(b.z, b.w)));
    #pragma unroll
    for (int o = 16; o; o >>= 1) m = fmaxf(m, __shfl_xor_sync(0xffffffffu, m, o));
    a.x = __expf(a.x - m); a.y = __expf(a.y - m); a.z = __expf(a.z - m); a.w = __expf(a.w - m);
    b.x = __expf(b.x - m); b.y = __expf(b.y - m); b.z = __expf(b.z - m); b.w = __expf(b.w - m);
    float s = a.x + a.y + a.z + a.w + b.x + b.y + b.z + b.w;
    #pragma unroll
    for (int o = 16; o; o >>= 1) s += __shfl_xor_sync(0xffffffffu, s, o);
    float inv = 1.0f / s;
    a.x *= inv; a.y *= inv; a.z *= inv; a.w *= inv;
    b.x *= inv; b.y *= inv; b.z *= inv; b.w *= inv;
    *reinterpret_cast<float4*>(&r[lane * 4]) = a;
    *reinterpret_cast<float4*>(&r[128 + lane * 4]) = b;
}

// ======================================================================
// tf32 mma GEMM, cp.async 3-stage pipeline.
// C[8192,512] = A[8192,512] @ Bt[512,512]^T (+bias)(+relu)(+resid)
// A and Bt are tf32-rounded with k permuted (within 32-blocks) by producers.
// flags: bit0 = relu, bit1 = perm+round the output (for W2's A input).
// ======================================================================
#define TGM 128
#define TGN 64
#define TBK 32
#define SSTR 36                 // floats per smem row (conflict-free)
#define STAGES 3
#define ASTG (TGM * SSTR)       // 4608 floats
#define BSTG (TGN * SSTR)       // 2304 floats
#define NKT  (D_ / TBK)         // 16
#define TG_SMEM (STAGES * (ASTG + BSTG) * 4)  // 82944 bytes

__device__ __forceinline__ void mma_tf32(float c[4],
                                         float a0, float a1, float a2, float a3,
                                         float b0, float b1)
{
    asm volatile(
        "mma.sync.aligned.m16n8k8.row.col.f32.tf32.tf32.f32 "
        "{%0,%1,%2,%3}, {%4,%5,%6,%7}, {%8,%9}, {%0,%1,%2,%3};"
        : "+f"(c[0]), "+f"(c[1]), "+f"(c[2]), "+f"(c[3])
        : "r"(__float_as_uint(a0)), "r"(__float_as_uint(a1)),
          "r"(__float_as_uint(a2)), "r"(__float_as_uint(a3)),
          "r"(__float_as_uint(b0)), "r"(__float_as_uint(b1)));
}

__global__ void __launch_bounds__(256, 2) tgemm_kernel(
    const float* __restrict__ A, const float* __restrict__ Bt,
    float* __restrict__ C, const float* __restrict__ bias,
    const float* __restrict__ resid, int flags)
{
    extern __shared__ float sm[];
    float* sA = sm;
    float* sB = sm + STAGES * ASTG;

    int tid = threadIdx.x, w = tid >> 5, lane = tid & 31;
    int g = lane >> 2, tig = lane & 3;
    int bm = blockIdx.y * TGM, bn = blockIdx.x * TGN;
    int wm = (w & 3) * 32, wn = (w >> 2) * 32;

    unsigned uA = (unsigned)__cvta_generic_to_shared(sA);
    unsigned uB = (unsigned)__cvta_generic_to_shared(sB);

    // per-thread copy coordinates
    int arow0 = tid >> 3, ac4 = tid & 7;       // + i*32 rows (4 iters)
    int brow0 = tid >> 3, bc4 = tid & 7;       // + i*32 rows (2 iters)

    float acc[2][4][4];
    #pragma unroll
    for (int i = 0; i < 2; i++)
        #pragma unroll
        for (int j = 0; j < 4; j++)
            #pragma unroll
            for (int q = 0; q < 4; q++) acc[i][j][q] = 0.f;

    // prologue: issue stages 0..2
    #pragma unroll
    for (int s = 0; s < STAGES; s++) {
        int kt0 = s * TBK;
        #pragma unroll
        for (int i = 0; i < 4; i++) {
            int row = arow0 + i * 32;
            const float* src = A + (long long)(bm + row) * D_ + kt0 + ac4 * 4;
            CP16(uA + (unsigned)((s * ASTG + row * SSTR + ac4 * 4) * 4), src);
        }
        #pragma unroll
        for (int i = 0; i < 2; i++) {
            int row = brow0 + i * 32;
            const float* src = Bt + (long long)(bn + row) * D_ + kt0 + bc4 * 4;
            CP16(uB + (unsigned)((s * BSTG + row * SSTR + bc4 * 4) * 4), src);
        }
        asm volatile("cp.async.commit_group;" ::: "memory");
    }

    for (int kt = 0; kt < NKT; kt++) {
        asm volatile("cp.async.wait_group 2;" ::: "memory");
        __syncthreads();
        int s = kt % STAGES;
        const float* dA = sA + s * ASTG;
        const float* dB = sB + s * BSTG;

        // fragment loads: 8 floats per row, contiguous thanks to k-perm
        float aA[4][8], bB[4][8];
        #pragma unroll
        for (int r = 0; r < 4; r++) {
            const float* rp = dA + (wm + g + r * 8) * SSTR + tig * 8;
            *reinterpret_cast<float4*>(&aA[r][0]) = *reinterpret_cast<const float4*>(rp);
            *reinterpret_cast<float4*>(&aA[r][4]) = *reinterpret_cast<const float4*>(rp + 4);
        }
        #pragma unroll
        for (int r = 0; r < 4; r++) {
            const float* rp = dB + (wn + g + r * 8) * SSTR + tig * 8;
            *reinterpret_cast<float4*>(&bB[r][0]) = *reinterpret_cast<const float4*>(rp);
            *reinterpret_cast<float4*>(&bB[r][4]) = *reinterpret_cast<const float4*>(rp + 4);
        }
        __syncthreads();

        // refill this stage with tile kt+3 (or empty commit to keep group count)
        if (kt + STAGES < NKT) {
            int kt0 = (kt + STAGES) * TBK;
            #pragma unroll
            for (int i = 0; i < 4; i++) {
                int row = arow0 + i * 32;
                const float* src = A + (long long)(bm + row) * D_ + kt0 + ac4 * 4;
                CP16(uA + (unsigned)((s * ASTG + row * SSTR + ac4 * 4) * 4), src);
            }
            #pragma unroll
            for (int i = 0; i < 2; i++) {
                int row = brow0 + i * 32;
                const float* src = Bt + (long long)(bn + row) * D_ + kt0 + bc4 * 4;
                CP16(uB + (unsigned)((s * BSTG + row * SSTR + bc4 * 4) * 4), src);
            }
        }
        asm volatile("cp.async.commit_group;" ::: "memory");

        // 32 MMAs on register fragments
        #pragma unroll
        for (int ks = 0; ks < 4; ks++) {
            #pragma unroll
            for (int mt = 0; mt < 2; mt++)
                #pragma unroll
                for (int nt = 0; nt < 4; nt++)
                    mma_tf32(acc[mt][nt],
                             aA[2 * mt][2 * ks], aA[2 * mt + 1][2 * ks],
                             aA[2 * mt][2 * ks + 1], aA[2 * mt + 1][2 * ks + 1],
                             bB[nt][2 * ks], bB[nt][2 * ks + 1]);
        }
    }

    // epilogue
    #pragma unroll
    for (int mt = 0; mt < 2; mt++) {
        #pragma unroll
        for (int nt = 0; nt < 4; nt++) {
            int row0 = bm + wm + mt * 16 + g;
            int col  = bn + wn + nt * 8 + 2 * tig;
            float2 bv = *reinterpret_cast<const float2*>(&bias[col]);
            float v00 = acc[mt][nt][0] + bv.x, v01 = acc[mt][nt][1] + bv.y;
            float v10 = acc[mt][nt][2] + bv.x, v11 = acc[mt][nt][3] + bv.y;
            if (flags & 1) {
                v00 = fmaxf(v00, 0.f); v01 = fmaxf(v01, 0.f);
                v10 = fmaxf(v10, 0.f); v11 = fmaxf(v11, 0.f);
            }
            if (resid) {
                float2 r0 = *reinterpret_cast<const float2*>(
                    &resid[(long long)row0 * D_ + col]);
                float2 r1 = *reinterpret_cast<const float2*>(
                    &resid[(long long)(row0 + 8) * D_ + col]);
                v00 += r0.x; v01 += r0.y; v10 += r1.x; v11 += r1.y;
            }
            if (flags & 2) {
                float* r0p = &C[(long long)row0 * D_];
                float* r1p = &C[(long long)(row0 + 8) * D_];
                st_perm(r0p, col, v00); st_perm(r0p, col + 1, v01);
                st_perm(r1p, col, v10); st_perm(r1p, col + 1, v11);
            } else {
                *reinterpret_cast<float2*>(&C[(long long)row0 * D_ + col]) =
                    make_float2(v00, v01);
                *reinterpret_cast<float2*>(&C[(long long)(row0 + 8) * D_ + col]) =
                    make_float2(v10, v11);
            }
        }
    }
}

// ---------------- scalar batched SGEMM (attention only) ----------------
#define BM 128
#define BN 64
#define BK 16

template<bool TRANSB>
__global__ void __launch_bounds__(256) gemm_kernel(
    const float* __restrict__ A, const float* __restrict__ B,
    float* __restrict__ C,
    int M, int N, int K, int lda, int ldb, int ldc,
    int innerB, long long sAo, long long sAi, long long sBo, long long sBi,
    long long sCo, long long sCi, float alpha, int permRound)
{
    __shared__ float As[BK][BM + 4];
    __shared__ float Bs[BK][BN + 4];
    int z  = blockIdx.z;
    int zo = z / innerB, zi = z - zo * innerB;
    A += zo * sAo + zi * sAi;
    B += zo * sBo + zi * sBi;
    C += zo * sCo + zi * sCi;

    int bm  = blockIdx.y * BM;
    int bn  = blockIdx.x * BN;
    int tid = threadIdx.x;
    int tx  = tid & 15, ty = tid >> 4;

    float acc[8][4];
    #pragma unroll
    for (int i = 0; i < 8; i++)
        #pragma unroll
        for (int j = 0; j < 4; j++) acc[i][j] = 0.f;

    for (int kt = 0; kt < K; kt += BK) {
        __syncthreads();
        #pragma unroll
        for (int i = 0; i < 2; i++) {
            int e = i * 256 + tid;
            int row = e >> 2, c4 = e & 3;
            float4 va = *reinterpret_cast<const float4*>(
                &A[(long long)(bm + row) * lda + kt + c4 * 4]);
            As[c4 * 4 + 0][row] = va.x;
            As[c4 * 4 + 1][row] = va.y;
            As[c4 * 4 + 2][row] = va.z;
            As[c4 * 4 + 3][row] = va.w;
        }
        if (TRANSB) {
            int n = tid >> 2, c4 = tid & 3;
            float4 vb = *reinterpret_cast<const float4*>(
                &B[(long long)(bn + n) * ldb + kt + c4 * 4]);
            Bs[c4 * 4 + 0][n] = vb.x;
            Bs[c4 * 4 + 1][n] = vb.y;
            Bs[c4 * 4 + 2][n] = vb.z;
            Bs[c4 * 4 + 3][n] = vb.w;
        } else {
            int r2 = tid >> 4, c4 = tid & 15;
            float4 vb = *reinterpret_cast<const float4*>(
                &B[(long long)(kt + r2) * ldb + bn + c4 * 4]);
            *reinterpret_cast<float4*>(&Bs[r2][c4 * 4]) = vb;
        }
        __syncthreads();
        #pragma unroll
        for (int kk = 0; kk < BK; kk++) {
            float4 a0 = *reinterpret_cast<const float4*>(&As[kk][ty * 8]);
            float4 a1 = *reinterpret_cast<const float4*>(&As[kk][ty * 8 + 4]);
            float4 bv = *reinterpret_cast<const float4*>(&Bs[kk][tx * 4]);
            float av[8] = {a0.x, a0.y, a0.z, a0.w, a1.x, a1.y, a1.z, a1.w};
            float bb[4] = {bv.x, bv.y, bv.z, bv.w};
            #pragma unroll
            for (int i = 0; i < 8; i++)
                #pragma unroll
                for (int j = 0; j < 4; j++)
                    acc[i][j] += av[i] * bb[j];
        }
    }

    #pragma unroll
    for (int i = 0; i < 8; i++) {
        int row = bm + ty * 8 + i;
        int col = bn + tx * 4;
        float vx = acc[i][0] * alpha, vy = acc[i][1] * alpha;
        float vz = acc[i][2] * alpha, vw = acc[i][3] * alpha;
        if (permRound) {
            float* rp = &C[(long long)row * ldc + (col & ~31)];
            int q = (col & 31) >> 2;
            rp[q]      = rndtf(vx);
            rp[8 + q]  = rndtf(vy);
            rp[16 + q] = rndtf(vz);
            rp[24 + q] = rndtf(vw);
        } else {
            *reinterpret_cast<float4*>(&C[(long long)row * ldc + col]) =
                make_float4(vx, vy, vz, vw);
        }
    }
}

// ---------------- PVAM head ----------------
__global__ void __launch_bounds__(256) pvam_kernel(
    const float* __restrict__ wf, const float* __restrict__ emb,
    const int* __restrict__ gwp, const float* __restrict__ fc1,
    float* __restrict__ out)
{
    __shared__ float s_wp[D_];
    __shared__ float s_f[D_];
    __shared__ float s_sc[T_];
    __shared__ float s_red[32];
    int m = blockIdx.x, b = blockIdx.y;
    int tid = threadIdx.x;
    int er = gwp[m];
    for (int i = tid; i < D_; i += 256) {
        s_wp[i] = emb[(long long)er * D_ + i];
        s_f[i]  = fc1[i];
    }
    __syncthreads();

    const float* wr = wf + ((long long)b * T_ + tid) * D_;
    float sc = 0.f;
    #pragma unroll 4
    for (int c4 = 0; c4 < D_ / 4; c4++) {
        float4 w = *reinterpret_cast<const float4*>(&wr[c4 * 4]);
        float4 p = *reinterpret_cast<const float4*>(&s_wp[c4 * 4]);
        float4 f = *reinterpret_cast<const float4*>(&s_f[c4 * 4]);
        sc += tanh_fast(w.x + p.x) * f.x;
        sc += tanh_fast(w.y + p.y) * f.y;
        sc += tanh_fast(w.z + p.z) * f.z;
        sc += tanh_fast(w.w + p.w) * f.w;
    }

    int wid = tid >> 5, lane = tid & 31;
    float mv = sc;
    #pragma unroll
    for (int o = 16; o; o >>= 1) mv = fmaxf(mv, __shfl_xor_sync(0xffffffffu, mv, o));
    if (lane == 0) s_red[wid] = mv;
    __syncthreads();
    if (tid < 32) {
        float t = (tid < 8) ? s_red[tid] : -3.0e38f;
        #pragma unroll
        for (int o = 4; o; o >>= 1) t = fmaxf(t, __shfl_xor_sync(0xffffffffu, t, o));
        if (tid == 0) s_red[8] = t;
    }
    __syncthreads();
    float bmax = s_red[8];
    float e = __expf(sc - bmax);
    float sv = e;
    #pragma unroll
    for (int o = 16; o; o >>= 1) sv += __shfl_xor_sync(0xffffffffu, sv, o);
    if (lane == 0) s_red[16 + wid] = sv;
    __syncthreads();
    if (tid < 32) {
        float t = (tid < 8) ? s_red[16 + tid] : 0.f;
        #pragma unroll
        for (int o = 4; o; o >>= 1) t += __shfl_xor_sync(0xffffffffu, t, o);
        if (tid == 0) s_red[25] = t;
    }
    __syncthreads();
    float inv = 1.0f / s_red[25];
    s_sc[tid] = e * inv;
    __syncthreads();

    long long base = (long long)b * T_ * D_;
    for (int c = tid; c < D_; c += 256) {
        float acc = 0.f;
        #pragma unroll 8
        for (int t = 0; t < T_; t++)
            acc += s_sc[t] * wf[base + (long long)t * D_ + c];
        out[(((long long)b * ML_) + m) * D_ + c] = acc;
    }
}

// ---------------- host launcher ----------------
extern "C" void kernel_launch(void* const* d_in, const int* in_sizes, int n_in,
                              void* d_out, int out_size)
{
    const float* x    = (const float*)d_in[0];
    const int*   ewp  = (const int*)  d_in[1];
    const int*   gwp  = (const int*)  d_in[2];
    const float* pos  = (const float*)d_in[3];
    const float* ln1s = (const float*)d_in[4];
    const float* ln1b = (const float*)d_in[5];
    const float* Wq   = (const float*)d_in[6];
    const float* bq   = (const float*)d_in[7];
    const float* Wk   = (const float*)d_in[8];
    const float* bk   = (const float*)d_in[9];
    const float* Wv   = (const float*)d_in[10];
    const float* bv   = (const float*)d_in[11];
    const float* Wo   = (const float*)d_in[12];
    const float* bo   = (const float*)d_in[13];
    const float* ln2s = (const float*)d_in[14];
    const float* ln2b = (const float*)d_in[15];
    const float* W1   = (const float*)d_in[16];
    const float* b1   = (const float*)d_in[17];
    const float* W2   = (const float*)d_in[18];
    const float* b2   = (const float*)d_in[19];
    const float* lnfs = (const float*)d_in[20];
    const float* lnfb = (const float*)d_in[21];
    const float* fc0w = (const float*)d_in[22];
    const float* fc0b = (const float*)d_in[23];
    const float* emb  = (const float*)d_in[24];
    const float* fc1  = (const float*)d_in[25];

    static float *enc = nullptr, *tmp, *q, *k, *v, *o, *p, *wT;
    if (!enc) {
        cudaGetSymbolAddress((void**)&enc, g_enc);
        cudaGetSymbolAddress((void**)&tmp, g_tmp);
        cudaGetSymbolAddress((void**)&q,   g_q);
        cudaGetSymbolAddress((void**)&k,   g_k);
        cudaGetSymbolAddress((void**)&v,   g_v);
        cudaGetSymbolAddress((void**)&o,   g_o);
        cudaGetSymbolAddress((void**)&p,   g_p);
        cudaGetSymbolAddress((void**)&wT,  g_wT);
        cudaFuncSetAttribute(tgemm_kernel,
                             cudaFuncAttributeMaxDynamicSharedMemorySize, TG_SMEM);
    }

    const long long DD = (long long)D_ * D_;

    WP wp;
    wp.w[0]  = Wq;       wp.w[1]  = Wk;       wp.w[2]  = Wv;
    wp.w[3]  = Wo;       wp.w[4]  = W1;       wp.w[5]  = W2;
    wp.w[6]  = Wq + DD;  wp.w[7]  = Wk + DD;  wp.w[8]  = Wv + DD;
    wp.w[9]  = Wo + DD;  wp.w[10] = W1 + DD;  wp.w[11] = W2 + DD;
    wp.w[12] = fc0w;
    wtrans_kernel<<<dim3(16, 16, NWMAT), dim3(32, 8)>>>(wp, wT);

    prep_kernel<<<dim3(D_ / 32, T_ / 32, B_), dim3(32, 8)>>>(x, pos, ewp, enc);

    const int MT = B_ * T_;   // 8192
    const dim3 tg(D_ / TGN, MT / TGM);  // (8, 64)

    for (int l = 0; l < L_; l++) {
        int vo = l * D_;
        const float* wq = wT + (l * 6 + 0) * DD;
        const float* wk = wT + (l * 6 + 1) * DD;
        const float* wv = wT + (l * 6 + 2) * DD;
        const float* wo = wT + (l * 6 + 3) * DD;
        const float* w1 = wT + (l * 6 + 4) * DD;
        const float* w2 = wT + (l * 6 + 5) * DD;

        ln_kernel<<<MT / 8, dim3(32, 8)>>>(enc, tmp, ln1s + vo, ln1b + vo);
        tgemm_kernel<<<tg, 256, TG_SMEM>>>(tmp, wq, q, bq + vo, nullptr, 0);
        tgemm_kernel<<<tg, 256, TG_SMEM>>>(tmp, wk, k, bk + vo, nullptr, 0);
        tgemm_kernel<<<tg, 256, TG_SMEM>>>(tmp, wv, v, bv + vo, nullptr, 0);

        // S = (Q K^T) / sqrt(dk), batched over (b,h)
        gemm_kernel<true><<<dim3(T_ / BN, T_ / BM, B_ * NH_), 256>>>(
            q, k, p, T_, T_, DK_, D_, D_, T_,
            NH_, (long long)T_ * D_, DK_, (long long)T_ * D_, DK_,
            (long long)NH_ * T_ * T_, (long long)T_ * T_, 0.125f, 0);
        softmax_kernel<<<(B_ * NH_ * T_) / 8, dim3(32, 8)>>>(p);
        // O = P V  (output perm+rounded: feeds tgemm Wo as A)
        gemm_kernel<false><<<dim3(DK_ / BN, T_ / BM, B_ * NH_), 256>>>(
            p, v, o, T_, DK_, T_, T_, D_, D_,
            NH_, (long long)NH_ * T_ * T_, (long long)T_ * T_,
            (long long)T_ * D_, DK_, (long long)T_ * D_, DK_, 1.f, 1);

        tgemm_kernel<<<tg, 256, TG_SMEM>>>(o, wo, enc, bo + vo, enc, 0);

        ln_kernel<<<MT / 8, dim3(32, 8)>>>(enc, tmp, ln2s + vo, ln2b + vo);
        tgemm_kernel<<<tg, 256, TG_SMEM>>>(tmp, w1, o, b1 + vo, nullptr, 3);  // relu + perm
        tgemm_kernel<<<tg, 256, TG_SMEM>>>(o, w2, enc, b2 + vo, enc, 0);
    }

    ln_kernel<<<MT / 8, dim3(32, 8)>>>(enc, tmp, lnfs, lnfb);
    tgemm_kernel<<<tg, 256, TG_SMEM>>>(tmp, wT + 12 * DD, q, fc0b, nullptr, 0);

    pvam_kernel<<<dim3(ML_, B_), 256>>>(q, emb, gwp, fc1, (float*)d_out);
}